// round 1
// baseline (speedup 1.0000x reference)
#include <cuda_runtime.h>
#include <cuda_bf16.h>
#include <math.h>

// ---------------- model constants ----------------
#define BS    64
#define T_    96
#define C_    16
#define IN_   16
#define H_    256
#define NH_   8
#define DH_   32
#define NCLS  4
#define L_    100          // T + NCLS
#define LAYERS 4
#define GDEP  2
#define BP    (BS * C_)    // 1024 sequences
#define ROWS  (BP * L_)    // 102400 token rows
#define EPS_  1e-5f

// ---------------- scratch (device globals; no allocs allowed) -------------
__device__ float g_h   [(size_t)ROWS * H_];        // 26.2M
__device__ float g_qkv [(size_t)ROWS * 3 * H_];    // 78.6M
__device__ float g_attn[(size_t)ROWS * H_];        // 26.2M
__device__ float g_tmp [(size_t)ROWS * 4 * H_];    // 104.8M (oproj / ff1 / ff2 staging)
__device__ float g_m1  [C_ * H_];
__device__ float g_m2  [C_ * H_];
__device__ float g_adj [C_ * C_];
__device__ float g_ho  [(size_t)BS * C_ * NCLS * 3 * H_];   // mixprop concat input (4096 x 768)
__device__ float g_mpo [(size_t)BS * C_ * NCLS * H_];       // mixprop gemm out    (4096 x 256)
__device__ float g_z   [(size_t)BS * C_ * NCLS * H_];       // tanh(cls) flattened (64 x 16384)
__device__ float g_d1  [BS * H_];

// ---------------- embed: h = [x@Wfc^T+bfc ; cls] + pos, swapaxes ----------
__global__ __launch_bounds__(256) void embed_kernel(
    const float* __restrict__ x, const float* __restrict__ Wfc,
    const float* __restrict__ bfc, const float* __restrict__ cls,
    const float* __restrict__ pos)
{
    int row = blockIdx.x;           // (b*16+c)*100 + l
    int l  = row % L_;
    int bc = row / L_;
    int c  = bc % C_;
    int b  = bc / C_;
    int t  = threadIdx.x;           // hd 0..255

    __shared__ float xs[IN_];
    float val;
    if (l < T_) {
        if (t < IN_) xs[t] = x[(((size_t)b * T_ + l) * C_ + c) * IN_ + t];
        __syncthreads();
        float s = bfc[t];
        #pragma unroll
        for (int i = 0; i < IN_; i++) s += xs[i] * Wfc[t * IN_ + i];
        val = s;
    } else {
        val = cls[((l - T_) * C_ + c) * H_ + t];
    }
    val += pos[((size_t)l * C_ + c) * H_ + t];
    g_h[(size_t)row * H_ + t] = val;
}

// ---------------- graph constructor (single block) ------------------------
__global__ __launch_bounds__(256) void graph_kernel(
    const float* __restrict__ emb1, const float* __restrict__ emb2,
    const float* __restrict__ Wl1, const float* __restrict__ bl1,
    const float* __restrict__ Wl2, const float* __restrict__ bl2)
{
    int t = threadIdx.x;
    for (int i = 0; i < C_; i++) {
        float s1 = bl1[t], s2 = bl2[t];
        for (int k = 0; k < H_; k++) {
            s1 += emb1[i * H_ + k] * Wl1[t * H_ + k];
            s2 += emb2[i * H_ + k] * Wl2[t * H_ + k];
        }
        g_m1[i * H_ + t] = tanhf(s1);
        g_m2[i * H_ + t] = tanhf(s2);
    }
    __syncthreads();

    __shared__ float adj[C_][C_];
    __shared__ float rsum[C_];
    int v = t >> 4, w = t & 15;
    float s = 0.f;
    for (int j = 0; j < H_; j++)
        s += g_m1[v * H_ + j] * g_m2[w * H_ + j]
           - g_m2[v * H_ + j] * g_m1[w * H_ + j];
    float gv = fmaxf(tanhf(s), 0.f);
    if (v == w) gv += 1.0f;            // adj = g + I
    adj[v][w] = gv;
    __syncthreads();
    if (t < C_) {
        float r = 0.f;
        for (int k = 0; k < C_; k++) r += adj[t][k];
        rsum[t] = r;
    }
    __syncthreads();
    g_adj[t] = adj[v][w] / rsum[v];
}

// ---------------- generic SGEMM: C[M,N] = A[M,K] @ B[N,K]^T + bias --------
// 128x128 tile, BK=8, 256 threads, 8x8 microtile. N and K must be %8; M guarded.
__global__ __launch_bounds__(256) void sgemm_kernel(
    const float* __restrict__ A, const float* __restrict__ B,
    const float* __restrict__ bias, float* __restrict__ C,
    int M, int N, int K, int relu)
{
    __shared__ float As[8][128];
    __shared__ float Bs[8][128];
    int tid = threadIdx.x;
    int tx = tid & 15;
    int ty = tid >> 4;
    int m0 = blockIdx.y * 128;
    int n0 = blockIdx.x * 128;
    int lrow = tid >> 1;            // 0..127
    int lcol = (tid & 1) * 4;       // 0 or 4
    const float* Aptr = A + (size_t)(m0 + lrow) * K + lcol;
    const float* Bptr = B + (size_t)(n0 + lrow) * K + lcol;
    bool aval = (m0 + lrow) < M;

    float acc[8][8];
    #pragma unroll
    for (int i = 0; i < 8; i++)
        #pragma unroll
        for (int j = 0; j < 8; j++) acc[i][j] = 0.f;

    for (int k0 = 0; k0 < K; k0 += 8) {
        float4 av = aval ? *reinterpret_cast<const float4*>(Aptr + k0)
                         : make_float4(0.f, 0.f, 0.f, 0.f);
        float4 bv = *reinterpret_cast<const float4*>(Bptr + k0);
        __syncthreads();
        As[lcol + 0][lrow] = av.x; As[lcol + 1][lrow] = av.y;
        As[lcol + 2][lrow] = av.z; As[lcol + 3][lrow] = av.w;
        Bs[lcol + 0][lrow] = bv.x; Bs[lcol + 1][lrow] = bv.y;
        Bs[lcol + 2][lrow] = bv.z; Bs[lcol + 3][lrow] = bv.w;
        __syncthreads();
        #pragma unroll
        for (int kk = 0; kk < 8; kk++) {
            float a[8], b[8];
            float4 a0 = *reinterpret_cast<const float4*>(&As[kk][ty * 8]);
            float4 a1 = *reinterpret_cast<const float4*>(&As[kk][ty * 8 + 4]);
            float4 b0 = *reinterpret_cast<const float4*>(&Bs[kk][tx * 8]);
            float4 b1 = *reinterpret_cast<const float4*>(&Bs[kk][tx * 8 + 4]);
            a[0]=a0.x; a[1]=a0.y; a[2]=a0.z; a[3]=a0.w;
            a[4]=a1.x; a[5]=a1.y; a[6]=a1.z; a[7]=a1.w;
            b[0]=b0.x; b[1]=b0.y; b[2]=b0.z; b[3]=b0.w;
            b[4]=b1.x; b[5]=b1.y; b[6]=b1.z; b[7]=b1.w;
            #pragma unroll
            for (int i = 0; i < 8; i++)
                #pragma unroll
                for (int j = 0; j < 8; j++)
                    acc[i][j] += a[i] * b[j];
        }
    }

    #pragma unroll
    for (int i = 0; i < 8; i++) {
        int m = m0 + ty * 8 + i;
        if (m >= M) continue;
        #pragma unroll
        for (int j = 0; j < 8; j++) {
            int n = n0 + tx * 8 + j;
            float v = acc[i][j] + bias[n];
            if (relu) v = fmaxf(v, 0.f);
            C[(size_t)m * N + n] = v;
        }
    }
}

// ---------------- attention: one block per (seq, head), online softmax ----
__global__ __launch_bounds__(128) void attn_kernel(
    const float* __restrict__ qkv, float* __restrict__ out)
{
    int bh = blockIdx.x;
    int b = bh >> 3;        // 0..1023
    int h = bh & 7;
    __shared__ float Ks[L_][DH_];
    __shared__ float Vs[L_][DH_];
    const float* base = qkv + (size_t)b * L_ * (3 * H_);
    for (int idx = threadIdx.x; idx < L_ * DH_; idx += 128) {
        int l = idx / DH_, d = idx % DH_;
        Ks[l][d] = base[(size_t)l * (3 * H_) + H_     + h * DH_ + d];
        Vs[l][d] = base[(size_t)l * (3 * H_) + 2 * H_ + h * DH_ + d];
    }
    __syncthreads();

    int i = threadIdx.x;
    if (i < L_) {
        float q[DH_];
        #pragma unroll
        for (int d = 0; d < DH_; d++)
            q[d] = base[(size_t)i * (3 * H_) + h * DH_ + d];
        float m = -1e30f, lsum = 0.f;
        float acc[DH_];
        #pragma unroll
        for (int d = 0; d < DH_; d++) acc[d] = 0.f;

        int jmax = (i >= T_) ? L_ : (i + 1);   // cls rows attend everywhere
        for (int j = 0; j < jmax; j++) {
            float s = 0.f;
            #pragma unroll
            for (int d = 0; d < DH_; d++) s += q[d] * Ks[j][d];
            s *= 0.17677669529663687f;         // 1/sqrt(32)
            float mnew = fmaxf(m, s);
            float sc = __expf(m - mnew);
            float p  = __expf(s - mnew);
            lsum = lsum * sc + p;
            #pragma unroll
            for (int d = 0; d < DH_; d++) acc[d] = acc[d] * sc + p * Vs[j][d];
            m = mnew;
        }
        float inv = 1.f / lsum;
        float* o = out + ((size_t)b * L_ + i) * H_ + h * DH_;
        #pragma unroll
        for (int d = 0; d < DH_; d++) o[d] = acc[d] * inv;
    }
}

// ---------------- fused residual-add + LayerNorm (H=256, 1 row/block) -----
__global__ __launch_bounds__(256) void add_ln_kernel(
    float* __restrict__ h, const float* __restrict__ x,
    const float* __restrict__ g, const float* __restrict__ bt)
{
    int row = blockIdx.x, t = threadIdx.x;
    size_t base = (size_t)row * H_;
    float v = h[base + t] + x[base + t];

    __shared__ float ws[8];
    float s = v;
    #pragma unroll
    for (int o = 16; o > 0; o >>= 1) s += __shfl_xor_sync(0xffffffffu, s, o);
    if ((t & 31) == 0) ws[t >> 5] = s;
    __syncthreads();
    float tot = 0.f;
    #pragma unroll
    for (int i = 0; i < 8; i++) tot += ws[i];
    float mean = tot * (1.0f / H_);
    float d = v - mean;
    __syncthreads();

    float q = d * d;
    #pragma unroll
    for (int o = 16; o > 0; o >>= 1) q += __shfl_xor_sync(0xffffffffu, q, o);
    if ((t & 31) == 0) ws[t >> 5] = q;
    __syncthreads();
    float qt = 0.f;
    #pragma unroll
    for (int i = 0; i < 8; i++) qt += ws[i];
    float var = qt * (1.0f / H_);

    h[base + t] = d * rsqrtf(var + EPS_) * g[t] + bt[t];
}

// ---------------- mixprop helpers -----------------------------------------
// gather cls rows into ho depth-0:  ho[(n,w,l)][0:256]
__global__ __launch_bounds__(256) void mp_gather_kernel()
{
    int idx = blockIdx.x * 256 + threadIdx.x;
    int hd = idx & 255;
    int r  = idx >> 8;              // (n*16+w)*4 + l
    int l  = r & 3;
    int nw = r >> 2;                // n*16 + w
    g_ho[(size_t)r * (3 * H_) + hd] =
        g_h[((size_t)nw * L_ + T_ + l) * H_ + hd];
}

// prop step: ho depth d from depth d-1 : out[n,v,l] = sum_w adj[v][w]*in[n,w,l]
__global__ __launch_bounds__(256) void mp_prop_kernel(int depth)
{
    int idx = blockIdx.x * 256 + threadIdx.x;
    int hd = idx & 255;
    int r  = idx >> 8;
    int l  = r & 3;
    int v  = (r >> 2) & 15;
    int n  = r >> 6;
    float s = 0.f;
    #pragma unroll
    for (int w = 0; w < C_; w++)
        s += g_adj[v * C_ + w] *
             g_ho[(size_t)(((n * C_ + w) << 2) + l) * (3 * H_) + (depth - 1) * H_ + hd];
    g_ho[(size_t)r * (3 * H_) + depth * H_ + hd] = s;
}

// scatter gemm result back into cls rows of h (bias already applied in gemm)
__global__ __launch_bounds__(256) void mp_scatter_kernel()
{
    int idx = blockIdx.x * 256 + threadIdx.x;
    int o  = idx & 255;
    int r  = idx >> 8;              // (n*16+w)*4 + l
    int l  = r & 3;
    int nw = r >> 2;
    g_h[((size_t)nw * L_ + T_ + l) * H_ + o] = g_mpo[(size_t)r * H_ + o];
}

// ---------------- final head ------------------------------------------------
__global__ __launch_bounds__(256) void tanh_gather_kernel()
{
    int idx = blockIdx.x * 256 + threadIdx.x;   // b*16384 + c*1024 + n*256 + hd
    int hd = idx & 255;
    int r  = idx >> 8;              // b*64 + c*4 + n
    int n  = r & 3;
    int c  = (r >> 2) & 15;
    int b  = r >> 6;
    g_z[idx] = tanhf(g_h[(((size_t)(b * C_ + c)) * L_ + T_ + n) * H_ + hd]);
}

__global__ __launch_bounds__(256) void head_kernel(
    const float* __restrict__ Wd2, const float* __restrict__ bd2,
    float* __restrict__ out)
{
    int b = blockIdx.x, t = threadIdx.x;
    float x = g_d1[b * H_ + t];
    float gl = 0.5f * x * (1.0f + erff(x * 0.70710678118654752f));   // exact gelu
    float v = gl * Wd2[t];
    #pragma unroll
    for (int o = 16; o > 0; o >>= 1) v += __shfl_xor_sync(0xffffffffu, v, o);
    __shared__ float ws[8];
    if ((t & 31) == 0) ws[t >> 5] = v;
    __syncthreads();
    if (t == 0) {
        float s = 0.f;
        #pragma unroll
        for (int i = 0; i < 8; i++) s += ws[i];
        out[b] = s + bd2[0];
    }
}

// ---------------- host-side device-symbol pointers -------------------------
static float* dev_ptr(const void* symbol)
{
    void* p = nullptr;
    cudaGetSymbolAddress(&p, symbol);
    return (float*)p;
}

extern "C" void kernel_launch(void* const* d_in, const int* in_sizes, int n_in,
                              void* d_out, int out_size)
{
    const float* x        = (const float*)d_in[0];
    const float* Wfc      = (const float*)d_in[3];
    const float* bfc      = (const float*)d_in[4];
    const float* cls_tok  = (const float*)d_in[5];
    const float* pos_emb  = (const float*)d_in[6];
    const float* emb1     = (const float*)d_in[7];
    const float* emb2     = (const float*)d_in[8];
    const float* Wl1      = (const float*)d_in[9];
    const float* bl1      = (const float*)d_in[10];
    const float* Wl2      = (const float*)d_in[11];
    const float* bl2      = (const float*)d_in[12];
    const float* Wqkv     = (const float*)d_in[13];
    const float* bqkv     = (const float*)d_in[14];
    const float* Wo       = (const float*)d_in[15];
    const float* bo       = (const float*)d_in[16];
    const float* W1       = (const float*)d_in[17];
    const float* b1       = (const float*)d_in[18];
    const float* W2       = (const float*)d_in[19];
    const float* b2       = (const float*)d_in[20];
    const float* ln1g     = (const float*)d_in[21];
    const float* ln1b     = (const float*)d_in[22];
    const float* ln2g     = (const float*)d_in[23];
    const float* ln2b     = (const float*)d_in[24];
    const float* Wmlp     = (const float*)d_in[25];
    const float* bmlp     = (const float*)d_in[26];
    const float* Wd1      = (const float*)d_in[27];
    const float* bd1      = (const float*)d_in[28];
    const float* Wd2      = (const float*)d_in[29];
    const float* bd2      = (const float*)d_in[30];
    float* out = (float*)d_out;

    static float *p_h = nullptr, *p_qkv, *p_attn, *p_tmp, *p_ho, *p_mpo, *p_z, *p_d1;
    if (!p_h) {
        p_h    = dev_ptr(g_h);
        p_qkv  = dev_ptr(g_qkv);
        p_attn = dev_ptr(g_attn);
        p_tmp  = dev_ptr(g_tmp);
        p_ho   = dev_ptr(g_ho);
        p_mpo  = dev_ptr(g_mpo);
        p_z    = dev_ptr(g_z);
        p_d1   = dev_ptr(g_d1);
    }

    // 0) graph constructor + embed
    graph_kernel<<<1, 256>>>(emb1, emb2, Wl1, bl1, Wl2, bl2);
    embed_kernel<<<ROWS, 256>>>(x, Wfc, bfc, cls_tok, pos_emb);

    const int MP_THREADS = BS * C_ * NCLS * H_;   // 1,048,576

    for (int l = 0; l < LAYERS; l++) {
        if (l > 0) {
            // --- mixprop on cls tokens ---
            mp_gather_kernel<<<MP_THREADS / 256, 256>>>();
            mp_prop_kernel<<<MP_THREADS / 256, 256>>>(1);
            mp_prop_kernel<<<MP_THREADS / 256, 256>>>(2);
            {
                dim3 grid(H_ / 128, (BS * C_ * NCLS + 127) / 128);
                sgemm_kernel<<<grid, 256>>>(p_ho,
                                            Wmlp + (size_t)(l - 1) * H_ * 3 * H_,
                                            bmlp + (size_t)(l - 1) * H_,
                                            p_mpo,
                                            BS * C_ * NCLS, H_, 3 * H_, 0);
            }
            mp_scatter_kernel<<<MP_THREADS / 256, 256>>>();
        }

        // --- QKV projection ---
        {
            dim3 grid((3 * H_) / 128, ROWS / 128);
            sgemm_kernel<<<grid, 256>>>(p_h,
                                        Wqkv + (size_t)l * 3 * H_ * H_,
                                        bqkv + (size_t)l * 3 * H_,
                                        p_qkv, ROWS, 3 * H_, H_, 0);
        }
        // --- attention ---
        attn_kernel<<<BP * NH_, 128>>>(p_qkv, p_attn);
        // --- output projection -> g_tmp ---
        {
            dim3 grid(H_ / 128, ROWS / 128);
            sgemm_kernel<<<grid, 256>>>(p_attn,
                                        Wo + (size_t)l * H_ * H_,
                                        bo + (size_t)l * H_,
                                        p_tmp, ROWS, H_, H_, 0);
        }
        add_ln_kernel<<<ROWS, 256>>>(p_h, p_tmp, ln1g + l * H_, ln1b + l * H_);

        // --- FFN ---
        {
            dim3 grid((4 * H_) / 128, ROWS / 128);
            sgemm_kernel<<<grid, 256>>>(p_h,
                                        W1 + (size_t)l * 4 * H_ * H_,
                                        b1 + (size_t)l * 4 * H_,
                                        p_tmp, ROWS, 4 * H_, H_, 1);
        }
        {
            dim3 grid(H_ / 128, ROWS / 128);
            sgemm_kernel<<<grid, 256>>>(p_tmp,
                                        W2 + (size_t)l * H_ * 4 * H_,
                                        b2 + (size_t)l * H_,
                                        p_attn, ROWS, H_, 4 * H_, 0);
        }
        add_ln_kernel<<<ROWS, 256>>>(p_h, p_attn, ln2g + l * H_, ln2b + l * H_);
    }

    // --- head ---
    tanh_gather_kernel<<<MP_THREADS / 256, 256>>>();
    {
        dim3 grid(H_ / 128, (BS + 127) / 128);
        sgemm_kernel<<<grid, 256>>>(p_z, Wd1, bd1, p_d1,
                                    BS, H_, C_ * NCLS * H_, 0);
    }
    head_kernel<<<BS, 256>>>(Wd2, bd2, out);
}

// round 7
// speedup vs baseline: 2.3043x; 2.3043x over previous
#include <cuda_runtime.h>
#include <cuda_bf16.h>
#include <math.h>
#include <stdint.h>

// ---------------- model constants ----------------
#define BS    64
#define T_    96
#define C_    16
#define IN_   16
#define H_    256
#define NH_   8
#define DH_   32
#define NCLS  4
#define L_    100          // T + NCLS
#define LAYERS 4
#define BP    (BS * C_)    // 1024 sequences
#define ROWS  (BP * L_)    // 102400 token rows
#define EPS_  1e-5f

// ================= low-level helpers =================
__device__ __forceinline__ uint32_t smem_u32(const void* p) {
    uint32_t a;
    asm("{ .reg .u64 t; cvta.to.shared.u64 t, %1; cvt.u32.u64 %0, t; }"
        : "=r"(a) : "l"(p));
    return a;
}
__device__ __forceinline__ void cp16(uint32_t dst, const void* src) {
    asm volatile("cp.async.cg.shared.global [%0], [%1], 16;" :: "r"(dst), "l"(src) : "memory");
}
__device__ __forceinline__ void ldsm4(uint32_t* r, uint32_t addr) {
    asm volatile("ldmatrix.sync.aligned.m8n8.x4.shared.b16 {%0,%1,%2,%3}, [%4];"
        : "=r"(r[0]), "=r"(r[1]), "=r"(r[2]), "=r"(r[3]) : "r"(addr));
}
__device__ __forceinline__ void ldsm2(uint32_t* r, uint32_t addr) {
    asm volatile("ldmatrix.sync.aligned.m8n8.x2.shared.b16 {%0,%1}, [%2];"
        : "=r"(r[0]), "=r"(r[1]) : "r"(addr));
}
__device__ __forceinline__ void mma16816(float* d, const uint32_t* a, const uint32_t* b) {
    asm volatile("mma.sync.aligned.m16n8k16.row.col.f32.bf16.bf16.f32 "
        "{%0,%1,%2,%3}, {%4,%5,%6,%7}, {%8,%9}, {%0,%1,%2,%3};"
        : "+f"(d[0]), "+f"(d[1]), "+f"(d[2]), "+f"(d[3])
        : "r"(a[0]), "r"(a[1]), "r"(a[2]), "r"(a[3]), "r"(b[0]), "r"(b[1]));
}

// ---------------- bf16 split helper ----------------
__device__ __forceinline__ void split_bf16(float v, __nv_bfloat16& hi, __nv_bfloat16& lo) {
    hi = __float2bfloat16(v);
    lo = __float2bfloat16(v - __bfloat162float(hi));
}

// ---------------- scratch (device globals) -------------
__device__ __align__(256) float         g_h  [(size_t)ROWS * H_];
__device__ __align__(256) __nv_bfloat16 g_hh [(size_t)ROWS * H_];
__device__ __align__(256) __nv_bfloat16 g_hl [(size_t)ROWS * H_];
__device__ __align__(256) float         g_qkv[(size_t)ROWS * 3 * H_];
__device__ __align__(256) __nv_bfloat16 g_ah [(size_t)ROWS * H_];
__device__ __align__(256) __nv_bfloat16 g_al [(size_t)ROWS * H_];
__device__ __align__(256) float         g_t1 [(size_t)ROWS * H_];
__device__ __align__(256) __nv_bfloat16 g_f1h[(size_t)ROWS * 4 * H_];
__device__ __align__(256) __nv_bfloat16 g_f1l[(size_t)ROWS * 4 * H_];
// weights (bf16 pairs)
__device__ __align__(256) __nv_bfloat16 g_wqkvh[LAYERS * 3 * H_ * H_], g_wqkvl[LAYERS * 3 * H_ * H_];
__device__ __align__(256) __nv_bfloat16 g_woh  [LAYERS * H_ * H_],     g_wol  [LAYERS * H_ * H_];
__device__ __align__(256) __nv_bfloat16 g_w1h  [LAYERS * 4 * H_ * H_], g_w1l  [LAYERS * 4 * H_ * H_];
__device__ __align__(256) __nv_bfloat16 g_w2h  [LAYERS * 4 * H_ * H_], g_w2l  [LAYERS * 4 * H_ * H_];
__device__ __align__(256) __nv_bfloat16 g_wmh  [(LAYERS-1) * H_ * 3 * H_], g_wml[(LAYERS-1) * H_ * 3 * H_];
// graph / mixprop
__device__ float g_m1 [C_ * H_];
__device__ float g_m2 [C_ * H_];
__device__ float g_adj[C_ * C_];
__device__ __align__(256) float         g_ho [(size_t)BS * C_ * NCLS * 3 * H_];
__device__ __align__(256) __nv_bfloat16 g_hoh[(size_t)BS * C_ * NCLS * 3 * H_];
__device__ __align__(256) __nv_bfloat16 g_hol[(size_t)BS * C_ * NCLS * 3 * H_];
__device__ __align__(256) float g_mpo[(size_t)BS * C_ * NCLS * H_];
__device__ __align__(256) float g_z  [(size_t)BS * C_ * NCLS * H_];
__device__ float g_d1 [BS * H_];

// ================= HMMA GEMM (bf16x3, mma.sync) =================
// C[M,N] = A[M,K] @ B[N,K]^T + bias.  mode 0: fp32 out; mode 1: relu + bf16 pair.
// grid = (N/128, M/128), 256 threads. M,N %128 == 0, K %32 == 0.
#define ASTR    40                        // bf16 row pitch (80B) — conflict-free for ldmatrix
#define TILE_B  (128 * ASTR * 2)          // 10240 bytes per buffer
#define STAGE_B (4 * TILE_B)              // Ah, Al, Bh, Bl
#define SMEM_GEMM_BYTES (2 * STAGE_B)     // 81920
#define OFF_AH  0
#define OFF_AL  TILE_B
#define OFF_BH  (2 * TILE_B)
#define OFF_BL  (3 * TILE_B)

__global__ __launch_bounds__(256) void gemm_bf3_kernel(
    const __nv_bfloat16* __restrict__ Ah, const __nv_bfloat16* __restrict__ Al,
    const __nv_bfloat16* __restrict__ Bh, const __nv_bfloat16* __restrict__ Bl,
    const float* __restrict__ bias,
    float* __restrict__ Cf, __nv_bfloat16* __restrict__ Ch, __nv_bfloat16* __restrict__ Cl,
    int M, int N, int K, int mode)
{
    extern __shared__ char smem[];
    uint32_t sb = smem_u32(smem);
    int tid = threadIdx.x;
    int lane = tid & 31;
    int w = tid >> 5;
    int wm = w >> 2;            // 0..1
    int wn = w & 3;             // 0..3
    int m0 = blockIdx.y * 128, n0 = blockIdx.x * 128;

    float acc[4][4][4];
    #pragma unroll
    for (int i = 0; i < 4; i++)
        #pragma unroll
        for (int j = 0; j < 4; j++)
            #pragma unroll
            for (int k = 0; k < 4; k++) acc[i][j][k] = 0.f;

    int nch = K >> 5;

    // ---- stage loader ----
    // 128 rows x 32 bf16 per buffer; thread handles 2 x 16B per buffer.
    #define ISSUE_STAGE(cidx) do {                                               \
        int _s = (cidx) & 1; int _kc = (cidx) << 5;                              \
        uint32_t _base = sb + _s * STAGE_B;                                      \
        _Pragma("unroll")                                                        \
        for (int _i = 0; _i < 2; _i++) {                                         \
            int _id = tid + _i * 256;                                            \
            int _r = _id >> 2;                                                   \
            int _cc = (_id & 3) << 3;                                            \
            uint32_t _do = (uint32_t)(_r * (ASTR * 2) + _cc * 2);                \
            size_t _ga = (size_t)(m0 + _r) * K + _kc + _cc;                      \
            size_t _gb = (size_t)(n0 + _r) * K + _kc + _cc;                      \
            cp16(_base + OFF_AH + _do, Ah + _ga);                                \
            cp16(_base + OFF_AL + _do, Al + _ga);                                \
            cp16(_base + OFF_BH + _do, Bh + _gb);                                \
            cp16(_base + OFF_BL + _do, Bl + _gb);                                \
        }                                                                        \
        asm volatile("cp.async.commit_group;" ::: "memory");                     \
    } while (0)

    ISSUE_STAGE(0);

    for (int c = 0; c < nch; c++) {
        if (c + 1 < nch) {
            ISSUE_STAGE(c + 1);
            asm volatile("cp.async.wait_group 1;" ::: "memory");
        } else {
            asm volatile("cp.async.wait_group 0;" ::: "memory");
        }
        __syncthreads();

        uint32_t base = sb + (c & 1) * STAGE_B;
        #pragma unroll
        for (int ks = 0; ks < 2; ks++) {
            uint32_t ah[4][4], al[4][4], bh[4][2], bl[4][2];
            int arow = wm * 64 + (lane & 15);
            int akc  = ks * 16 + (lane >> 4) * 8;
            #pragma unroll
            for (int mf = 0; mf < 4; mf++) {
                uint32_t off = (uint32_t)(((arow + mf * 16) * ASTR + akc) * 2);
                ldsm4(ah[mf], base + OFF_AH + off);
                ldsm4(al[mf], base + OFF_AL + off);
            }
            int brow = wn * 32 + (lane & 7);
            int bkc  = ks * 16 + (((lane & 15) >> 3)) * 8;
            #pragma unroll
            for (int nf = 0; nf < 4; nf++) {
                uint32_t off = (uint32_t)(((brow + nf * 8) * ASTR + bkc) * 2);
                ldsm2(bh[nf], base + OFF_BH + off);
                ldsm2(bl[nf], base + OFF_BL + off);
            }
            #pragma unroll
            for (int mf = 0; mf < 4; mf++)
                #pragma unroll
                for (int nf = 0; nf < 4; nf++) {
                    mma16816(acc[mf][nf], ah[mf], bh[nf]);
                    mma16816(acc[mf][nf], ah[mf], bl[nf]);
                    mma16816(acc[mf][nf], al[mf], bh[nf]);
                }
        }
        __syncthreads();
    }

    // ---- epilogue ----
    int rbase = m0 + wm * 64 + (lane >> 2);
    int cbase = n0 + wn * 32 + (lane & 3) * 2;
    #pragma unroll
    for (int mf = 0; mf < 4; mf++) {
        #pragma unroll
        for (int nf = 0; nf < 4; nf++) {
            int r = rbase + mf * 16;
            int cc = cbase + nf * 8;
            float b0 = bias[cc], b1 = bias[cc + 1];
            if (mode == 0) {
                float2 v0 = { acc[mf][nf][0] + b0, acc[mf][nf][1] + b1 };
                float2 v1 = { acc[mf][nf][2] + b0, acc[mf][nf][3] + b1 };
                *(float2*)(Cf + (size_t)r * N + cc)       = v0;
                *(float2*)(Cf + (size_t)(r + 8) * N + cc) = v1;
            } else {
                float v0 = fmaxf(acc[mf][nf][0] + b0, 0.f);
                float v1 = fmaxf(acc[mf][nf][1] + b1, 0.f);
                float v2 = fmaxf(acc[mf][nf][2] + b0, 0.f);
                float v3 = fmaxf(acc[mf][nf][3] + b1, 0.f);
                __nv_bfloat16 h0, l0, h1, l1, h2, l2, h3, l3;
                split_bf16(v0, h0, l0); split_bf16(v1, h1, l1);
                split_bf16(v2, h2, l2); split_bf16(v3, h3, l3);
                __nv_bfloat162 hh0; hh0.x = h0; hh0.y = h1;
                __nv_bfloat162 ll0; ll0.x = l0; ll0.y = l1;
                __nv_bfloat162 hh1; hh1.x = h2; hh1.y = h3;
                __nv_bfloat162 ll1; ll1.x = l2; ll1.y = l3;
                *(__nv_bfloat162*)(Ch + (size_t)r * N + cc)       = hh0;
                *(__nv_bfloat162*)(Cl + (size_t)r * N + cc)       = ll0;
                *(__nv_bfloat162*)(Ch + (size_t)(r + 8) * N + cc) = hh1;
                *(__nv_bfloat162*)(Cl + (size_t)(r + 8) * N + cc) = ll1;
            }
        }
    }
}

// ================= misc kernels =================
__global__ __launch_bounds__(256) void conv_pair_kernel(
    const float* __restrict__ s, __nv_bfloat16* __restrict__ hi,
    __nv_bfloat16* __restrict__ lo, int n)
{
    int i = blockIdx.x * 256 + threadIdx.x;
    if (i < n) {
        __nv_bfloat16 h, l;
        split_bf16(s[i], h, l);
        hi[i] = h; lo[i] = l;
    }
}

__global__ __launch_bounds__(256) void embed_kernel(
    const float* __restrict__ x, const float* __restrict__ Wfc,
    const float* __restrict__ bfc, const float* __restrict__ cls,
    const float* __restrict__ pos)
{
    int row = blockIdx.x;
    int l  = row % L_;
    int bc = row / L_;
    int c  = bc % C_;
    int b  = bc / C_;
    int t  = threadIdx.x;

    __shared__ float xs[IN_];
    float val;
    if (l < T_) {
        if (t < IN_) xs[t] = x[(((size_t)b * T_ + l) * C_ + c) * IN_ + t];
        __syncthreads();
        float s = bfc[t];
        #pragma unroll
        for (int i = 0; i < IN_; i++) s += xs[i] * Wfc[t * IN_ + i];
        val = s;
    } else {
        val = cls[((l - T_) * C_ + c) * H_ + t];
    }
    val += pos[((size_t)l * C_ + c) * H_ + t];
    size_t o = (size_t)row * H_ + t;
    g_h[o] = val;
    __nv_bfloat16 h, lo_;
    split_bf16(val, h, lo_);
    g_hh[o] = h; g_hl[o] = lo_;
}

__global__ __launch_bounds__(256) void graph_kernel(
    const float* __restrict__ emb1, const float* __restrict__ emb2,
    const float* __restrict__ Wl1, const float* __restrict__ bl1,
    const float* __restrict__ Wl2, const float* __restrict__ bl2)
{
    int t = threadIdx.x;
    for (int i = 0; i < C_; i++) {
        float s1 = bl1[t], s2 = bl2[t];
        for (int k = 0; k < H_; k++) {
            s1 += emb1[i * H_ + k] * Wl1[t * H_ + k];
            s2 += emb2[i * H_ + k] * Wl2[t * H_ + k];
        }
        g_m1[i * H_ + t] = tanhf(s1);
        g_m2[i * H_ + t] = tanhf(s2);
    }
    __syncthreads();

    __shared__ float adj[C_][C_];
    __shared__ float rsum[C_];
    int v = t >> 4, w = t & 15;
    float s = 0.f;
    for (int j = 0; j < H_; j++)
        s += g_m1[v * H_ + j] * g_m2[w * H_ + j]
           - g_m2[v * H_ + j] * g_m1[w * H_ + j];
    float gv = fmaxf(tanhf(s), 0.f);
    if (v == w) gv += 1.0f;
    adj[v][w] = gv;
    __syncthreads();
    if (t < C_) {
        float r = 0.f;
        for (int k = 0; k < C_; k++) r += adj[t][k];
        rsum[t] = r;
    }
    __syncthreads();
    g_adj[t] = adj[v][w] / rsum[v];
}

// attention: block per (seq, head); writes bf16 pair for O-proj input
__global__ __launch_bounds__(128) void attn_kernel(const float* __restrict__ qkv)
{
    int bh = blockIdx.x;
    int b = bh >> 3;
    int h = bh & 7;
    __shared__ float Ks[L_][DH_];
    __shared__ float Vs[L_][DH_];
    const float* base = qkv + (size_t)b * L_ * (3 * H_);
    for (int idx = threadIdx.x; idx < L_ * DH_; idx += 128) {
        int l = idx / DH_, d = idx % DH_;
        Ks[l][d] = base[(size_t)l * (3 * H_) + H_     + h * DH_ + d];
        Vs[l][d] = base[(size_t)l * (3 * H_) + 2 * H_ + h * DH_ + d];
    }
    __syncthreads();

    int i = threadIdx.x;
    if (i < L_) {
        float q[DH_];
        #pragma unroll
        for (int d = 0; d < DH_; d++)
            q[d] = base[(size_t)i * (3 * H_) + h * DH_ + d];
        float m = -1e30f, lsum = 0.f;
        float acc[DH_];
        #pragma unroll
        for (int d = 0; d < DH_; d++) acc[d] = 0.f;

        int jmax = (i >= T_) ? L_ : (i + 1);
        for (int j = 0; j < jmax; j++) {
            float s = 0.f;
            #pragma unroll
            for (int d = 0; d < DH_; d++) s += q[d] * Ks[j][d];
            s *= 0.17677669529663687f;
            if (s <= m) {
                float p = __expf(s - m);
                lsum += p;
                #pragma unroll
                for (int d = 0; d < DH_; d++) acc[d] += p * Vs[j][d];
            } else {
                float sc = __expf(m - s);
                lsum = lsum * sc + 1.f;
                #pragma unroll
                for (int d = 0; d < DH_; d++) acc[d] = acc[d] * sc + Vs[j][d];
                m = s;
            }
        }
        float inv = 1.f / lsum;
        size_t o = ((size_t)b * L_ + i) * H_ + h * DH_;
        #pragma unroll
        for (int d = 0; d < DH_; d++) {
            __nv_bfloat16 hh, ll;
            split_bf16(acc[d] * inv, hh, ll);
            g_ah[o + d] = hh; g_al[o + d] = ll;
        }
    }
}

// fused residual-add + LayerNorm; writes fp32 h and bf16 pair
__global__ __launch_bounds__(256) void add_ln_kernel(
    const float* __restrict__ xin,
    const float* __restrict__ g, const float* __restrict__ bt)
{
    int row = blockIdx.x, t = threadIdx.x;
    size_t base = (size_t)row * H_;
    float v = g_h[base + t] + xin[base + t];

    __shared__ float ws[8];
    float s = v;
    #pragma unroll
    for (int o = 16; o > 0; o >>= 1) s += __shfl_xor_sync(0xffffffffu, s, o);
    if ((t & 31) == 0) ws[t >> 5] = s;
    __syncthreads();
    float tot = 0.f;
    #pragma unroll
    for (int i = 0; i < 8; i++) tot += ws[i];
    float mean = tot * (1.0f / H_);
    float d = v - mean;
    __syncthreads();

    float q = d * d;
    #pragma unroll
    for (int o = 16; o > 0; o >>= 1) q += __shfl_xor_sync(0xffffffffu, q, o);
    if ((t & 31) == 0) ws[t >> 5] = q;
    __syncthreads();
    float qt = 0.f;
    #pragma unroll
    for (int i = 0; i < 8; i++) qt += ws[i];
    float var = qt * (1.0f / H_);

    float out = d * rsqrtf(var + EPS_) * g[t] + bt[t];
    g_h[base + t] = out;
    __nv_bfloat16 hh, ll;
    split_bf16(out, hh, ll);
    g_hh[base + t] = hh; g_hl[base + t] = ll;
}

// ---------------- mixprop helpers -----------------
__global__ __launch_bounds__(256) void mp_gather_kernel()
{
    int idx = blockIdx.x * 256 + threadIdx.x;
    int hd = idx & 255;
    int r  = idx >> 8;
    int l  = r & 3;
    int nw = r >> 2;
    g_ho[(size_t)r * (3 * H_) + hd] = g_h[((size_t)nw * L_ + T_ + l) * H_ + hd];
}

__global__ __launch_bounds__(256) void mp_prop_kernel(int depth)
{
    int idx = blockIdx.x * 256 + threadIdx.x;
    int hd = idx & 255;
    int r  = idx >> 8;
    int l  = r & 3;
    int v  = (r >> 2) & 15;
    int n  = r >> 6;
    float s = 0.f;
    #pragma unroll
    for (int w = 0; w < C_; w++)
        s += g_adj[v * C_ + w] *
             g_ho[(size_t)(((n * C_ + w) << 2) + l) * (3 * H_) + (depth - 1) * H_ + hd];
    g_ho[(size_t)r * (3 * H_) + depth * H_ + hd] = s;
}

__global__ __launch_bounds__(256) void mp_scatter_kernel()
{
    int idx = blockIdx.x * 256 + threadIdx.x;
    int o  = idx & 255;
    int r  = idx >> 8;
    int l  = r & 3;
    int nw = r >> 2;
    float v = g_mpo[(size_t)r * H_ + o];
    size_t dst = ((size_t)nw * L_ + T_ + l) * H_ + o;
    g_h[dst] = v;
    __nv_bfloat16 hh, ll;
    split_bf16(v, hh, ll);
    g_hh[dst] = hh; g_hl[dst] = ll;
}

// ---------------- head ----------------
__global__ __launch_bounds__(256) void tanh_gather_kernel()
{
    int idx = blockIdx.x * 256 + threadIdx.x;
    int hd = idx & 255;
    int r  = idx >> 8;
    int n  = r & 3;
    int c  = (r >> 2) & 15;
    int b  = r >> 6;
    g_z[idx] = tanhf(g_h[(((size_t)(b * C_ + c)) * L_ + T_ + n) * H_ + hd]);
}

// 64 blocks (per batch), 512 threads; z row cached in SMEM (64KB)
__global__ __launch_bounds__(512) void head_gemm_kernel(
    const float* __restrict__ Wd1, const float* __restrict__ bd1)
{
    extern __shared__ float zs[];
    int b = blockIdx.x;
    int tid = threadIdx.x;
    for (int i = tid; i < C_ * NCLS * H_; i += 512)
        zs[i] = g_z[(size_t)b * (C_ * NCLS * H_) + i];
    __syncthreads();
    int wid = tid >> 5, lane = tid & 31;
    for (int o = wid; o < H_; o += 16) {
        const float* w = Wd1 + (size_t)o * (C_ * NCLS * H_);
        float s = 0.f;
        for (int k = lane; k < C_ * NCLS * H_; k += 32)
            s += zs[k] * w[k];
        #pragma unroll
        for (int off = 16; off > 0; off >>= 1)
            s += __shfl_xor_sync(0xffffffffu, s, off);
        if (lane == 0) g_d1[b * H_ + o] = s + bd1[o];
    }
}

__global__ __launch_bounds__(256) void head_kernel(
    const float* __restrict__ Wd2, const float* __restrict__ bd2,
    float* __restrict__ out)
{
    int b = blockIdx.x, t = threadIdx.x;
    float x = g_d1[b * H_ + t];
    float gl = 0.5f * x * (1.0f + erff(x * 0.70710678118654752f));
    float v = gl * Wd2[t];
    #pragma unroll
    for (int o = 16; o > 0; o >>= 1) v += __shfl_xor_sync(0xffffffffu, v, o);
    __shared__ float ws[8];
    if ((t & 31) == 0) ws[t >> 5] = v;
    __syncthreads();
    if (t == 0) {
        float s = 0.f;
        #pragma unroll
        for (int i = 0; i < 8; i++) s += ws[i];
        out[b] = s + bd2[0];
    }
}

// ---------------- host ----------------
static float* dev_ptr(const void* symbol)
{
    void* p = nullptr;
    cudaGetSymbolAddress(&p, symbol);
    return (float*)p;
}
static __nv_bfloat16* dev_ptr_b(const void* symbol)
{
    void* p = nullptr;
    cudaGetSymbolAddress(&p, symbol);
    return (__nv_bfloat16*)p;
}

extern "C" void kernel_launch(void* const* d_in, const int* in_sizes, int n_in,
                              void* d_out, int out_size)
{
    const float* x        = (const float*)d_in[0];
    const float* Wfc      = (const float*)d_in[3];
    const float* bfc      = (const float*)d_in[4];
    const float* cls_tok  = (const float*)d_in[5];
    const float* pos_emb  = (const float*)d_in[6];
    const float* emb1     = (const float*)d_in[7];
    const float* emb2     = (const float*)d_in[8];
    const float* Wl1      = (const float*)d_in[9];
    const float* bl1      = (const float*)d_in[10];
    const float* Wl2      = (const float*)d_in[11];
    const float* bl2      = (const float*)d_in[12];
    const float* Wqkv     = (const float*)d_in[13];
    const float* bqkv     = (const float*)d_in[14];
    const float* Wo       = (const float*)d_in[15];
    const float* bo       = (const float*)d_in[16];
    const float* W1       = (const float*)d_in[17];
    const float* b1       = (const float*)d_in[18];
    const float* W2       = (const float*)d_in[19];
    const float* b2       = (const float*)d_in[20];
    const float* ln1g     = (const float*)d_in[21];
    const float* ln1b     = (const float*)d_in[22];
    const float* ln2g     = (const float*)d_in[23];
    const float* ln2b     = (const float*)d_in[24];
    const float* Wmlp     = (const float*)d_in[25];
    const float* bmlp     = (const float*)d_in[26];
    const float* Wd1      = (const float*)d_in[27];
    const float* bd1      = (const float*)d_in[28];
    const float* Wd2      = (const float*)d_in[29];
    const float* bd2      = (const float*)d_in[30];
    float* out = (float*)d_out;

    static bool inited = false;
    static float *p_h, *p_qkv, *p_t1, *p_mpo, *p_ho;
    static __nv_bfloat16 *p_hh, *p_hl, *p_ah, *p_al, *p_f1h, *p_f1l;
    static __nv_bfloat16 *p_wqkvh, *p_wqkvl, *p_woh, *p_wol, *p_w1h, *p_w1l,
                         *p_w2h, *p_w2l, *p_wmh, *p_wml, *p_hoh, *p_hol;
    if (!inited) {
        cudaFuncSetAttribute(gemm_bf3_kernel,
            cudaFuncAttributeMaxDynamicSharedMemorySize, SMEM_GEMM_BYTES);
        cudaFuncSetAttribute(head_gemm_kernel,
            cudaFuncAttributeMaxDynamicSharedMemorySize, C_ * NCLS * H_ * 4);
        p_h = dev_ptr(g_h); p_qkv = dev_ptr(g_qkv); p_t1 = dev_ptr(g_t1);
        p_mpo = dev_ptr(g_mpo); p_ho = dev_ptr(g_ho);
        p_hh = dev_ptr_b(g_hh); p_hl = dev_ptr_b(g_hl);
        p_ah = dev_ptr_b(g_ah); p_al = dev_ptr_b(g_al);
        p_f1h = dev_ptr_b(g_f1h); p_f1l = dev_ptr_b(g_f1l);
        p_wqkvh = dev_ptr_b(g_wqkvh); p_wqkvl = dev_ptr_b(g_wqkvl);
        p_woh = dev_ptr_b(g_woh); p_wol = dev_ptr_b(g_wol);
        p_w1h = dev_ptr_b(g_w1h); p_w1l = dev_ptr_b(g_w1l);
        p_w2h = dev_ptr_b(g_w2h); p_w2l = dev_ptr_b(g_w2l);
        p_wmh = dev_ptr_b(g_wmh); p_wml = dev_ptr_b(g_wml);
        p_hoh = dev_ptr_b(g_hoh); p_hol = dev_ptr_b(g_hol);
        inited = true;
    }

    // weight conversion (fp32 -> bf16 hi/lo)
    conv_pair_kernel<<<(LAYERS * 3 * H_ * H_) / 256, 256>>>(Wqkv, p_wqkvh, p_wqkvl, LAYERS * 3 * H_ * H_);
    conv_pair_kernel<<<(LAYERS * H_ * H_) / 256, 256>>>(Wo, p_woh, p_wol, LAYERS * H_ * H_);
    conv_pair_kernel<<<(LAYERS * 4 * H_ * H_) / 256, 256>>>(W1, p_w1h, p_w1l, LAYERS * 4 * H_ * H_);
    conv_pair_kernel<<<(LAYERS * 4 * H_ * H_) / 256, 256>>>(W2, p_w2h, p_w2l, LAYERS * 4 * H_ * H_);
    conv_pair_kernel<<<((LAYERS - 1) * H_ * 3 * H_) / 256, 256>>>(Wmlp, p_wmh, p_wml, (LAYERS - 1) * H_ * 3 * H_);

    graph_kernel<<<1, 256>>>(emb1, emb2, Wl1, bl1, Wl2, bl2);
    embed_kernel<<<ROWS, 256>>>(x, Wfc, bfc, cls_tok, pos_emb);

    const int MP_THREADS = BS * C_ * NCLS * H_;   // 1,048,576
    const int HO_N = BS * C_ * NCLS * 3 * H_;     // 3,145,728

    for (int l = 0; l < LAYERS; l++) {
        if (l > 0) {
            mp_gather_kernel<<<MP_THREADS / 256, 256>>>();
            mp_prop_kernel<<<MP_THREADS / 256, 256>>>(1);
            mp_prop_kernel<<<MP_THREADS / 256, 256>>>(2);
            conv_pair_kernel<<<HO_N / 256, 256>>>(p_ho, p_hoh, p_hol, HO_N);
            gemm_bf3_kernel<<<dim3(2, 32), 256, SMEM_GEMM_BYTES>>>(
                p_hoh, p_hol,
                p_wmh + (size_t)(l - 1) * H_ * 3 * H_, p_wml + (size_t)(l - 1) * H_ * 3 * H_,
                bmlp + (size_t)(l - 1) * H_,
                p_mpo, nullptr, nullptr,
                BS * C_ * NCLS, H_, 3 * H_, 0);
            mp_scatter_kernel<<<MP_THREADS / 256, 256>>>();
        }

        // QKV projection
        gemm_bf3_kernel<<<dim3(6, ROWS / 128), 256, SMEM_GEMM_BYTES>>>(
            p_hh, p_hl,
            p_wqkvh + (size_t)l * 3 * H_ * H_, p_wqkvl + (size_t)l * 3 * H_ * H_,
            bqkv + (size_t)l * 3 * H_,
            p_qkv, nullptr, nullptr, ROWS, 3 * H_, H_, 0);

        attn_kernel<<<BP * NH_, 128>>>(p_qkv);

        // output projection -> g_t1
        gemm_bf3_kernel<<<dim3(2, ROWS / 128), 256, SMEM_GEMM_BYTES>>>(
            p_ah, p_al,
            p_woh + (size_t)l * H_ * H_, p_wol + (size_t)l * H_ * H_,
            bo + (size_t)l * H_,
            p_t1, nullptr, nullptr, ROWS, H_, H_, 0);

        add_ln_kernel<<<ROWS, 256>>>(p_t1, ln1g + l * H_, ln1b + l * H_);

        // FFN
        gemm_bf3_kernel<<<dim3(8, ROWS / 128), 256, SMEM_GEMM_BYTES>>>(
            p_hh, p_hl,
            p_w1h + (size_t)l * 4 * H_ * H_, p_w1l + (size_t)l * 4 * H_ * H_,
            b1 + (size_t)l * 4 * H_,
            nullptr, p_f1h, p_f1l, ROWS, 4 * H_, H_, 1);

        gemm_bf3_kernel<<<dim3(2, ROWS / 128), 256, SMEM_GEMM_BYTES>>>(
            p_f1h, p_f1l,
            p_w2h + (size_t)l * 4 * H_ * H_, p_w2l + (size_t)l * 4 * H_ * H_,
            b2 + (size_t)l * H_,
            p_t1, nullptr, nullptr, ROWS, H_, 4 * H_, 0);

        add_ln_kernel<<<ROWS, 256>>>(p_t1, ln2g + l * H_, ln2b + l * H_);
    }

    tanh_gather_kernel<<<MP_THREADS / 256, 256>>>();
    head_gemm_kernel<<<BS, 512, C_ * NCLS * H_ * 4>>>(Wd1, bd1);
    head_kernel<<<BS, 256>>>(Wd2, bd2, out);
}